// round 13
// baseline (speedup 1.0000x reference)
#include <cuda_runtime.h>

#define NUM_LEVELS 16
#define TABLE_SZ   16384
#define CHUNKS     9
#define NBLK       144            // 9 chunks x 16 levels, 1 CTA/SM
#define THREADS    1024
#define MAX_B      262144

// floor(16 * 1.38^l) computed in double precision, exactly representable in f32
__constant__ float c_res[NUM_LEVELS] = {
    16.f, 22.f, 30.f, 42.f, 58.f, 80.f, 110.f, 152.f,
    210.f, 290.f, 400.f, 553.f, 763.f, 1053.f, 1453.f, 2005.f
};

// Scratch (allocation-free rule: __device__ globals)
__device__ float4 g_xs[MAX_B];                  // packed positions (4 MB)
__device__ float2 g_scr[NUM_LEVELS * MAX_B];    // [level][b] features (33.5 MB)

// Grid barrier state (monotonic generation -> replay-safe, deterministic)
__device__ volatile unsigned g_gen = 0;
__device__ unsigned g_cnt = 0;

__device__ __forceinline__ void grid_barrier()
{
    __syncthreads();
    if (threadIdx.x == 0) {
        __threadfence();                          // flush + order my writes
        unsigned gen = g_gen;
        if (atomicAdd(&g_cnt, 1u) == NBLK - 1) {
            g_cnt = 0;
            __threadfence();
            g_gen = gen + 1;                      // release
        } else {
            while (g_gen == gen) { }              // volatile spin (L1-bypass)
        }
    }
    __syncthreads();
}

__device__ __forceinline__ void hash_point(const float2* __restrict__ s_tab,
                                           const float px, const float py,
                                           const float pz, const float res,
                                           float& ox, float& oy)
{
    // Interpolation weights use the UNSCALED position (faithful to source)
    const float wx = px - floorf(px);
    const float wy = py - floorf(py);
    const float wz = pz - floorf(pz);

    const float sx = res * px;
    const float sy = res * py;
    const float sz = res * pz;

    const int lx = __float2int_rd(sx);
    const int ly = __float2int_rd(sy);
    const int lz = __float2int_rd(sz);
    const int hx = __float2int_ru(sx);
    const int hy = __float2int_ru(sy);
    const int hz = __float2int_ru(sz);

    // int32 wraparound multiply == uint32 multiply (same bits);
    // python remainder by 16384 == & 16383 on two's complement
    const unsigned ay0 = 2654435761u * (unsigned)ly;
    const unsigned ay1 = 2654435761u * (unsigned)hy;
    const unsigned az0 = 805459861u  * (unsigned)lz;
    const unsigned az1 = 805459861u  * (unsigned)hz;

    const unsigned b00 = ay0 ^ az0;
    const unsigned b10 = ay1 ^ az0;
    const unsigned b01 = ay0 ^ az1;
    const unsigned b11 = ay1 ^ az1;
    const unsigned ux = (unsigned)lx;
    const unsigned vx = (unsigned)hx;

    // Corner order v0..v7: (0,0,0)(1,0,0)(1,1,0)(0,1,0)(0,0,1)(1,0,1)(1,1,1)(0,1,1)
    const float2 f0 = s_tab[(ux ^ b00) & 16383u];
    const float2 f1 = s_tab[(vx ^ b00) & 16383u];
    const float2 f2 = s_tab[(vx ^ b10) & 16383u];
    const float2 f3 = s_tab[(ux ^ b10) & 16383u];
    const float2 f4 = s_tab[(ux ^ b01) & 16383u];
    const float2 f5 = s_tab[(vx ^ b01) & 16383u];
    const float2 f6 = s_tab[(vx ^ b11) & 16383u];
    const float2 f7 = s_tab[(ux ^ b11) & 16383u];

    const float ex = 1.f - wx, ey = 1.f - wy, ez = 1.f - wz;
    const float w00 = ex * ey, w10 = wx * ey, w11 = wx * wy, w01 = ex * wy;
    const float c0 = w00 * ez, c1 = w10 * ez, c2 = w11 * ez, c3 = w01 * ez;
    const float c4 = w00 * wz, c5 = w10 * wz, c6 = w11 * wz, c7 = w01 * wz;

    float vxr = c0 * f0.x;
    vxr = fmaf(c1, f1.x, vxr);
    vxr = fmaf(c2, f2.x, vxr);
    vxr = fmaf(c3, f3.x, vxr);
    vxr = fmaf(c4, f4.x, vxr);
    vxr = fmaf(c5, f5.x, vxr);
    vxr = fmaf(c6, f6.x, vxr);
    vxr = fmaf(c7, f7.x, vxr);

    float vyr = c0 * f0.y;
    vyr = fmaf(c1, f1.y, vyr);
    vyr = fmaf(c2, f2.y, vyr);
    vyr = fmaf(c3, f3.y, vyr);
    vyr = fmaf(c4, f4.y, vyr);
    vyr = fmaf(c5, f5.y, vyr);
    vyr = fmaf(c6, f6.y, vyr);
    vyr = fmaf(c7, f7.y, vyr);

    ox = vxr;
    oy = vyr;
}

// smem layout: [0, 128K) table; [128K, 128K+65920) transpose tile / pack staging
#define SMEM_TOTAL (TABLE_SZ * 8 + NUM_LEVELS * 515 * 8)

extern __shared__ unsigned char smem_raw[];

__global__ __launch_bounds__(THREADS, 1)
void fused_kernel(const float4* __restrict__ x4,
                  const float* __restrict__ tables,
                  float4* __restrict__ out4, int B)
{
    float2* s_tab = reinterpret_cast<float2*>(smem_raw);
    const int bid = blockIdx.x;
    const int t   = threadIdx.x;

    const int level = bid / CHUNKS;        // 0..15
    const int chunk = bid % CHUNKS;        // 0..8

    // ---------------- Phase A: table fill + pack x (overlapped memory work)
    {
        const float4* src = reinterpret_cast<const float4*>(
            tables + (size_t)level * TABLE_SZ * 2);
        float4* dst = reinterpret_cast<float4*>(s_tab);
        #pragma unroll 4
        for (int i = t; i < TABLE_SZ / 2; i += THREADS)
            dst[i] = src[i];
    }
    {
        float*  sp  = reinterpret_cast<float*>(smem_raw + TABLE_SZ * 8);
        float4* st4 = reinterpret_cast<float4*>(sp);
        for (int tile = bid; tile * 2048 < B; tile += NBLK) {
            const int base = tile * 2048;
            const int len  = min(2048, B - base);   // B div by 4
            const int nf4  = (len * 3) >> 2;
            const float4* src = x4 + (((size_t)base * 3) >> 2);
            __syncthreads();
            for (int k = t; k < nf4; k += THREADS)
                st4[k] = src[k];
            __syncthreads();
            for (int p = t; p < len; p += THREADS)
                g_xs[base + p] =
                    make_float4(sp[3 * p], sp[3 * p + 1], sp[3 * p + 2], 0.f);
        }
    }

    grid_barrier();

    // ---------------- Phase B: hash + trilinear (exact R9 structure)
    {
        const float res = c_res[level];
        const int per   = (B + CHUNKS - 1) / CHUNKS;   // 29128 (even)
        const int start = chunk * per;
        const int end   = min(start + per, B);
        float2* __restrict__ scr = g_scr + (size_t)level * B;

        for (int b = start + 2 * t; b + 1 < end; b += 2 * THREADS) {
            const float4 p0 = g_xs[b];
            const float4 p1 = g_xs[b + 1];

            float ox0, oy0, ox1, oy1;
            hash_point(s_tab, p0.x, p0.y, p0.z, res, ox0, oy0);
            hash_point(s_tab, p1.x, p1.y, p1.z, res, ox1, oy1);

            reinterpret_cast<float4*>(scr + b)[0] =
                make_float4(ox0, oy0, ox1, oy1);
        }
    }

    grid_barrier();

    // ---------------- Phase C: transpose, 512-pt tiles, MLP=8 per thread
    {
        typedef float2 Row[515];
        Row* s = reinterpret_cast<Row*>(smem_raw + TABLE_SZ * 8);
        const int p  = t & 511;
        const int l0 = (t >> 9) * 8;       // 0 or 8

        for (int tile = bid; tile * 512 < B; tile += NBLK) {
            const int b0 = tile * 512;
            const int b  = b0 + p;
            __syncthreads();               // protect previous tile's reads
            if (b < B) {
                float2 v[8];
                #pragma unroll
                for (int i = 0; i < 8; i++)
                    v[i] = g_scr[(size_t)(l0 + i) * B + b];  // 8 indep loads
                #pragma unroll
                for (int i = 0; i < 8; i++)
                    s[l0 + i][p] = v[i];                     // conflict-free
            }
            __syncthreads();
            // 512 pts * 8 float4 = 4096 outputs, 4/thread, coalesced
            #pragma unroll
            for (int i = 0; i < 4; i++) {
                int o  = i * 1024 + t;     // 0..4095
                int pp = o >> 3;
                int j  = o & 7;
                if (b0 + pp < B) {
                    float2 a = s[2 * j + 0][pp];
                    float2 c = s[2 * j + 1][pp];
                    out4[(size_t)b0 * 8 + o] = make_float4(a.x, a.y, c.x, c.y);
                }
            }
        }
    }
}

extern "C" void kernel_launch(void* const* d_in, const int* in_sizes, int n_in,
                              void* d_out, int out_size)
{
    const float* x      = (const float*)d_in[0];
    const float* tables = (const float*)d_in[1];
    float4* out4        = (float4*)d_out;
    const int B = in_sizes[0] / 3;

    cudaFuncSetAttribute(fused_kernel,
                         cudaFuncAttributeMaxDynamicSharedMemorySize, SMEM_TOTAL);

    fused_kernel<<<NBLK, THREADS, SMEM_TOTAL>>>(
        (const float4*)x, tables, out4, B);
}